// round 1
// baseline (speedup 1.0000x reference)
#include <cuda_runtime.h>
#include <cstdint>
#include <math.h>

#define N_NODES 100000
#define N_EDGES 3200000
#define EPS_BN 1e-5f
#define EPS_NORM 1e-12f

// ---------------- device scratch (no allocation allowed) ----------------
__device__ __align__(16) float g_x0[N_NODES * 5];    // BN output
__device__ __align__(16) float g_x1[N_NODES * 64];   // conv1 output
__device__ __align__(16) float g_x2[N_NODES * 64];   // conv2 output
__device__ __align__(16) float g_y[N_NODES * 64];    // scatter source buffer (stride 64 or 8)
__device__ __align__(16) float g_agg[N_NODES * 64];  // conv2 accumulator
__device__ __align__(32) float g_agg8[N_NODES * 8];  // conv1/conv3 accumulator (5 feats + cnt)
__device__ float g_cinv[N_NODES];                    // 1/max(cnt,1)
__device__ float g_bnstats[16];                      // [0..4] sum, [5..9] sumsq

// ---------------- vector reductions ----------------
__device__ __forceinline__ void red_add_v4(float* p, float4 v) {
    asm volatile("red.global.add.v4.f32 [%0], {%1,%2,%3,%4};"
                 :: "l"(p), "f"(v.x), "f"(v.y), "f"(v.z), "f"(v.w) : "memory");
}
__device__ __forceinline__ void red_add_v2(float* p, float a, float b) {
    asm volatile("red.global.add.v2.f32 [%0], {%1,%2};"
                 :: "l"(p), "f"(a), "f"(b) : "memory");
}
__device__ __forceinline__ void red_add_f32(float* p, float a) {
    asm volatile("red.global.add.f32 [%0], %1;"
                 :: "l"(p), "f"(a) : "memory");
}

// ---------------- BatchNorm statistics ----------------
__global__ void bn_stats_kernel(const float* __restrict__ h) {
    float s[5] = {0, 0, 0, 0, 0}, q[5] = {0, 0, 0, 0, 0};
    int stride = gridDim.x * blockDim.x;
    for (int n = blockIdx.x * blockDim.x + threadIdx.x; n < N_NODES; n += stride) {
#pragma unroll
        for (int i = 0; i < 5; i++) {
            float v = h[n * 5 + i];
            s[i] += v;
            q[i] += v * v;
        }
    }
    // warp reduce
#pragma unroll
    for (int k = 16; k > 0; k >>= 1) {
#pragma unroll
        for (int i = 0; i < 5; i++) {
            s[i] += __shfl_down_sync(0xffffffffu, s[i], k);
            q[i] += __shfl_down_sync(0xffffffffu, q[i], k);
        }
    }
    __shared__ float sh[10];
    if (threadIdx.x < 10) sh[threadIdx.x] = 0.f;
    __syncthreads();
    if ((threadIdx.x & 31) == 0) {
#pragma unroll
        for (int i = 0; i < 5; i++) {
            atomicAdd(&sh[i], s[i]);
            atomicAdd(&sh[5 + i], q[i]);
        }
    }
    __syncthreads();
    if (threadIdx.x < 10) atomicAdd(&g_bnstats[threadIdx.x], sh[threadIdx.x]);
}

// ---------------- BN apply + conv1 projection (5x5) -> y8 ----------------
__global__ void bn_conv1_kernel(const float* __restrict__ h,
                                const float* __restrict__ gamma,
                                const float* __restrict__ beta,
                                const float* __restrict__ pw,
                                const float* __restrict__ pb,
                                float* __restrict__ x0,
                                float* __restrict__ y8) {
    int n = blockIdx.x * blockDim.x + threadIdx.x;
    if (n >= N_NODES) return;
    const float inv_n = 1.f / (float)N_NODES;
    float xr[5];
#pragma unroll
    for (int i = 0; i < 5; i++) {
        float mu = g_bnstats[i] * inv_n;
        float var = g_bnstats[5 + i] * inv_n - mu * mu;
        float sc = rsqrtf(var + EPS_BN) * gamma[i];
        float v = (h[n * 5 + i] - mu) * sc + beta[i];
        xr[i] = v;
        x0[n * 5 + i] = v;
    }
#pragma unroll
    for (int k = 0; k < 5; k++) {
        float v = pb[k];
#pragma unroll
        for (int i = 0; i < 5; i++) v += xr[i] * pw[i * 5 + k];
        y8[n * 8 + k] = fmaxf(v, 0.f);
    }
}

// ---------------- width-8 scatter (conv1 with cnt, conv3 without) ----------------
template <bool ADD_CNT>
__global__ void scatter8_kernel(const int* __restrict__ src,
                                const int* __restrict__ dst,
                                const float* __restrict__ ew,
                                const float* __restrict__ y8,
                                float* __restrict__ agg8) {
    int stride = gridDim.x * blockDim.x;
    for (int e = blockIdx.x * blockDim.x + threadIdx.x; e < N_EDGES; e += stride) {
        int s = __ldg(&src[e]);
        int d = __ldg(&dst[e]);
        float w = __ldg(&ew[e]);
        float4 a = *reinterpret_cast<const float4*>(y8 + s * 8);
        float v4 = __ldg(&y8[s * 8 + 4]);
        a.x *= w; a.y *= w; a.z *= w; a.w *= w;
        red_add_v4(agg8 + d * 8, a);
        if (ADD_CNT)
            red_add_v2(agg8 + d * 8 + 4, v4 * w, 1.0f);
        else
            red_add_f32(agg8 + d * 8 + 4, v4 * w);
    }
}

// ---------------- width-64 scatter (conv2): warp handles 2 edges ----------------
__global__ void scatter64_kernel(const int* __restrict__ src,
                                 const int* __restrict__ dst,
                                 const float* __restrict__ ew,
                                 const float* __restrict__ y,
                                 float* __restrict__ agg) {
    int lane = threadIdx.x & 31;
    int warp = (blockIdx.x * blockDim.x + threadIdx.x) >> 5;
    int nwarps = (gridDim.x * blockDim.x) >> 5;
    int half = lane >> 4;         // which edge of the pair
    int f = (lane & 15) << 2;     // feature offset (float4 granule)
    const int npairs = N_EDGES / 2;
    for (int p = warp; p < npairs; p += nwarps) {
        int e = 2 * p + half;
        int s = __ldg(&src[e]);
        int d = __ldg(&dst[e]);
        float w = __ldg(&ew[e]);
        float4 v = *reinterpret_cast<const float4*>(y + s * 64 + f);
        v.x *= w; v.y *= w; v.z *= w; v.w *= w;
        red_add_v4(agg + d * 64 + f, v);
    }
}

// ---------------- conv1 finalize: out64 = mean5@lw + lb + x0@rw ; norm ; relu ----------------
__global__ void fin1_kernel(const float* __restrict__ x0,
                            const float* __restrict__ agg8,
                            const float* __restrict__ lw,
                            const float* __restrict__ lb,
                            const float* __restrict__ rw,
                            float* __restrict__ x1,
                            float* __restrict__ cinv_out) {
    int t = threadIdx.x;
    int nl = t >> 6;           // 0..3 local node
    int o = t & 63;            // output feature
    int n = blockIdx.x * 4 + nl;
    float c = agg8[n * 8 + 5];
    float ci = 1.f / fmaxf(c, 1.f);
    if (o == 0) cinv_out[n] = ci;
    float out = lb[o];
#pragma unroll
    for (int i = 0; i < 5; i++) {
        out += (agg8[n * 8 + i] * ci) * lw[i * 64 + o] + x0[n * 5 + i] * rw[i * 64 + o];
    }
    float ss = out * out;
#pragma unroll
    for (int k = 16; k > 0; k >>= 1) ss += __shfl_down_sync(0xffffffffu, ss, k);
    __shared__ float sp[8];
    int w = t >> 5;
    if ((t & 31) == 0) sp[w] = ss;
    __syncthreads();
    float tot = sp[nl * 2] + sp[nl * 2 + 1];
    float sc = 1.f / fmaxf(sqrtf(tot), EPS_NORM);
    x1[n * 64 + o] = fmaxf(out * sc, 0.f);
}

// ---------------- y = relu(x@pw + pb) @ lw  (64 -> 64 -> OUT2) ----------------
template <int OUT2>
__global__ __launch_bounds__(128) void proj_lw_kernel(const float* __restrict__ x,
                                                      const float* __restrict__ pw,
                                                      const float* __restrict__ pb,
                                                      const float* __restrict__ lw,
                                                      float* __restrict__ y) {
    constexpr int OUTP = (OUT2 == 64) ? 64 : 8;
    constexpr int YS = (OUT2 == 64) ? 64 : 8;
    constexpr int NPB = 32;
    constexpr int XS = 36;  // padded transposed stride
    __shared__ float s_w[64 * 64];
    __shared__ float s_x[64 * XS];
    __shared__ float s_xp[64 * XS];
    __shared__ float s_pb[64];
    const int t = threadIdx.x;
    const int n0 = blockIdx.x * NPB;

    for (int i4 = t; i4 < 1024; i4 += 128)
        reinterpret_cast<float4*>(s_w)[i4] = reinterpret_cast<const float4*>(pw)[i4];
    if (t < 64) s_pb[t] = pb[t];
    for (int idx = t; idx < NPB * 64; idx += 128) {
        int n = idx >> 6, i = idx & 63;
        s_x[i * XS + n] = x[(n0 + n) * 64 + i];
    }
    __syncthreads();

    const int oq = t & 15, nq = t >> 4;
    float acc[4][4];
#pragma unroll
    for (int a = 0; a < 4; a++)
#pragma unroll
        for (int b = 0; b < 4; b++) acc[a][b] = 0.f;

#pragma unroll 8
    for (int i = 0; i < 64; i++) {
        float4 xv = *reinterpret_cast<const float4*>(&s_x[i * XS + (nq << 2)]);
        float4 wv = *reinterpret_cast<const float4*>(&s_w[(i << 6) + (oq << 2)]);
        acc[0][0] += xv.x * wv.x; acc[0][1] += xv.x * wv.y; acc[0][2] += xv.x * wv.z; acc[0][3] += xv.x * wv.w;
        acc[1][0] += xv.y * wv.x; acc[1][1] += xv.y * wv.y; acc[1][2] += xv.y * wv.z; acc[1][3] += xv.y * wv.w;
        acc[2][0] += xv.z * wv.x; acc[2][1] += xv.z * wv.y; acc[2][2] += xv.z * wv.z; acc[2][3] += xv.z * wv.w;
        acc[3][0] += xv.w * wv.x; acc[3][1] += xv.w * wv.y; acc[3][2] += xv.w * wv.z; acc[3][3] += xv.w * wv.w;
    }
#pragma unroll
    for (int dk = 0; dk < 4; dk++) {
        float b = s_pb[(oq << 2) + dk];
#pragma unroll
        for (int dn = 0; dn < 4; dn++) {
            s_xp[((oq << 2) + dk) * XS + (nq << 2) + dn] = fmaxf(acc[dn][dk] + b, 0.f);
        }
    }
    __syncthreads();

    if (OUT2 == 64) {
        for (int i4 = t; i4 < 1024; i4 += 128)
            reinterpret_cast<float4*>(s_w)[i4] = reinterpret_cast<const float4*>(lw)[i4];
    } else {
        for (int idx = t; idx < 64 * 8; idx += 128) s_w[idx] = 0.f;
        __syncthreads();
        for (int idx = t; idx < 64 * 5; idx += 128) s_w[(idx / 5) * 8 + (idx % 5)] = lw[idx];
    }
    __syncthreads();

    constexpr int OQ2 = OUTP / 4;
    if (oq < OQ2) {
        float a2[4][4];
#pragma unroll
        for (int a = 0; a < 4; a++)
#pragma unroll
            for (int b = 0; b < 4; b++) a2[a][b] = 0.f;
#pragma unroll 8
        for (int i = 0; i < 64; i++) {
            float4 xv = *reinterpret_cast<const float4*>(&s_xp[i * XS + (nq << 2)]);
            float4 wv = *reinterpret_cast<const float4*>(&s_w[i * OUTP + (oq << 2)]);
            a2[0][0] += xv.x * wv.x; a2[0][1] += xv.x * wv.y; a2[0][2] += xv.x * wv.z; a2[0][3] += xv.x * wv.w;
            a2[1][0] += xv.y * wv.x; a2[1][1] += xv.y * wv.y; a2[1][2] += xv.y * wv.z; a2[1][3] += xv.y * wv.w;
            a2[2][0] += xv.z * wv.x; a2[2][1] += xv.z * wv.y; a2[2][2] += xv.z * wv.z; a2[2][3] += xv.z * wv.w;
            a2[3][0] += xv.w * wv.x; a2[3][1] += xv.w * wv.y; a2[3][2] += xv.w * wv.z; a2[3][3] += xv.w * wv.w;
        }
#pragma unroll
        for (int dn = 0; dn < 4; dn++) {
            float4 o4 = make_float4(a2[dn][0], a2[dn][1], a2[dn][2], a2[dn][3]);
            *reinterpret_cast<float4*>(&y[(n0 + (nq << 2) + dn) * YS + (oq << 2)]) = o4;
        }
    }
}

// ---------------- conv2 finalize: out = agg*cinv + lb + x@rw ; norm ; relu ----------------
__global__ __launch_bounds__(128) void fin64_kernel(const float* __restrict__ x,
                                                    const float* __restrict__ agg,
                                                    const float* __restrict__ cinv,
                                                    const float* __restrict__ rw,
                                                    const float* __restrict__ lb,
                                                    float* __restrict__ out) {
    constexpr int NPB = 32;
    constexpr int XS = 36;
    __shared__ float s_w[64 * 64];
    __shared__ float s_x[64 * XS];
    __shared__ float s_lb[64];
    const int t = threadIdx.x;
    const int n0 = blockIdx.x * NPB;

    for (int i4 = t; i4 < 1024; i4 += 128)
        reinterpret_cast<float4*>(s_w)[i4] = reinterpret_cast<const float4*>(rw)[i4];
    if (t < 64) s_lb[t] = lb[t];
    for (int idx = t; idx < NPB * 64; idx += 128) {
        int n = idx >> 6, i = idx & 63;
        s_x[i * XS + n] = x[(n0 + n) * 64 + i];
    }
    __syncthreads();

    const int oq = t & 15, nq = t >> 4;
    float acc[4][4];
#pragma unroll
    for (int a = 0; a < 4; a++)
#pragma unroll
        for (int b = 0; b < 4; b++) acc[a][b] = 0.f;
#pragma unroll 8
    for (int i = 0; i < 64; i++) {
        float4 xv = *reinterpret_cast<const float4*>(&s_x[i * XS + (nq << 2)]);
        float4 wv = *reinterpret_cast<const float4*>(&s_w[(i << 6) + (oq << 2)]);
        acc[0][0] += xv.x * wv.x; acc[0][1] += xv.x * wv.y; acc[0][2] += xv.x * wv.z; acc[0][3] += xv.x * wv.w;
        acc[1][0] += xv.y * wv.x; acc[1][1] += xv.y * wv.y; acc[1][2] += xv.y * wv.z; acc[1][3] += xv.y * wv.w;
        acc[2][0] += xv.z * wv.x; acc[2][1] += xv.z * wv.y; acc[2][2] += xv.z * wv.z; acc[2][3] += xv.z * wv.w;
        acc[3][0] += xv.w * wv.x; acc[3][1] += xv.w * wv.y; acc[3][2] += xv.w * wv.z; acc[3][3] += xv.w * wv.w;
    }

    float lb0 = s_lb[(oq << 2) + 0], lb1 = s_lb[(oq << 2) + 1];
    float lb2 = s_lb[(oq << 2) + 2], lb3 = s_lb[(oq << 2) + 3];
#pragma unroll
    for (int dn = 0; dn < 4; dn++) {
        int n = n0 + (nq << 2) + dn;
        float ci = cinv[n];
        float4 ag = *reinterpret_cast<const float4*>(&agg[n * 64 + (oq << 2)]);
        float v0 = acc[dn][0] + lb0 + ag.x * ci;
        float v1 = acc[dn][1] + lb1 + ag.y * ci;
        float v2 = acc[dn][2] + lb2 + ag.z * ci;
        float v3 = acc[dn][3] + lb3 + ag.w * ci;
        float ss = v0 * v0 + v1 * v1 + v2 * v2 + v3 * v3;
        // reduce across the 16 oq-threads of this node (a half-warp segment)
        ss += __shfl_down_sync(0xffffffffu, ss, 8, 16);
        ss += __shfl_down_sync(0xffffffffu, ss, 4, 16);
        ss += __shfl_down_sync(0xffffffffu, ss, 2, 16);
        ss += __shfl_down_sync(0xffffffffu, ss, 1, 16);
        ss = __shfl_sync(0xffffffffu, ss, 0, 16);
        float sc = 1.f / fmaxf(sqrtf(ss), EPS_NORM);
        float4 o4 = make_float4(fmaxf(v0 * sc, 0.f), fmaxf(v1 * sc, 0.f),
                                fmaxf(v2 * sc, 0.f), fmaxf(v3 * sc, 0.f));
        *reinterpret_cast<float4*>(&out[n * 64 + (oq << 2)]) = o4;
    }
}

// ---------------- conv3 finalize: out5 = agg*cinv + lb + x2@rw ; norm (no relu) ----------------
__global__ void fin3_kernel(const float* __restrict__ x2,
                            const float* __restrict__ agg8,
                            const float* __restrict__ cinv,
                            const float* __restrict__ rw,
                            const float* __restrict__ lb,
                            float* __restrict__ out) {
    int t = threadIdx.x;
    int n = blockIdx.x * 16 + (t >> 3);
    int j = t & 7;
    float ci = cinv[n];
    float v = 0.f;
    if (j < 5) {
        v = lb[j] + agg8[n * 8 + j] * ci;
        const float* xr = x2 + (size_t)n * 64;
#pragma unroll 8
        for (int i = 0; i < 64; i++) v += xr[i] * rw[i * 5 + j];
    }
    float ss = (j < 5) ? v * v : 0.f;
    ss += __shfl_down_sync(0xffffffffu, ss, 4, 8);
    ss += __shfl_down_sync(0xffffffffu, ss, 2, 8);
    ss += __shfl_down_sync(0xffffffffu, ss, 1, 8);
    ss = __shfl_sync(0xffffffffu, ss, 0, 8);
    if (j < 5) out[n * 5 + j] = v / fmaxf(sqrtf(ss), EPS_NORM);
}

// ---------------- host launcher ----------------
extern "C" void kernel_launch(void* const* d_in, const int* in_sizes, int n_in,
                              void* d_out, int out_size) {
    const float* h = (const float*)d_in[0];
    const int* ei = (const int*)d_in[1];
    const float* ew = (const float*)d_in[2];
    const float* gamma = (const float*)d_in[3];
    const float* beta = (const float*)d_in[4];
    const float* c1_pw = (const float*)d_in[5];
    const float* c1_pb = (const float*)d_in[6];
    const float* c1_lw = (const float*)d_in[7];
    const float* c1_lb = (const float*)d_in[8];
    const float* c1_rw = (const float*)d_in[9];
    const float* c2_pw = (const float*)d_in[10];
    const float* c2_pb = (const float*)d_in[11];
    const float* c2_lw = (const float*)d_in[12];
    const float* c2_lb = (const float*)d_in[13];
    const float* c2_rw = (const float*)d_in[14];
    const float* c3_pw = (const float*)d_in[15];
    const float* c3_pb = (const float*)d_in[16];
    const float* c3_lw = (const float*)d_in[17];
    const float* c3_lb = (const float*)d_in[18];
    const float* c3_rw = (const float*)d_in[19];
    float* out = (float*)d_out;

    const int* src = ei;
    const int* dst = ei + N_EDGES;

    float *x0, *x1, *x2, *y, *agg, *agg8, *cinv, *stats;
    cudaGetSymbolAddress((void**)&x0, g_x0);
    cudaGetSymbolAddress((void**)&x1, g_x1);
    cudaGetSymbolAddress((void**)&x2, g_x2);
    cudaGetSymbolAddress((void**)&y, g_y);
    cudaGetSymbolAddress((void**)&agg, g_agg);
    cudaGetSymbolAddress((void**)&agg8, g_agg8);
    cudaGetSymbolAddress((void**)&cinv, g_cinv);
    cudaGetSymbolAddress((void**)&stats, g_bnstats);

    cudaMemsetAsync(agg, 0, sizeof(float) * N_NODES * 64, 0);
    cudaMemsetAsync(agg8, 0, sizeof(float) * N_NODES * 8, 0);
    cudaMemsetAsync(stats, 0, sizeof(float) * 16, 0);

    // BatchNorm
    bn_stats_kernel<<<128, 256>>>(h);
    bn_conv1_kernel<<<(N_NODES + 255) / 256, 256>>>(h, gamma, beta, c1_pw, c1_pb, x0, y);

    // conv1: scatter xp (width 5) + cnt, then finalize (lw applied to mean)
    scatter8_kernel<true><<<6250, 256>>>(src, dst, ew, y, agg8);
    fin1_kernel<<<N_NODES / 4, 256>>>(x0, agg8, c1_lw, c1_lb, c1_rw, x1, cinv);

    // conv2: y = relu(x1@pw+pb)@lw (width 64), scatter, finalize
    proj_lw_kernel<64><<<N_NODES / 32, 128>>>(x1, c2_pw, c2_pb, c2_lw, y);
    scatter64_kernel<<<4096, 256>>>(src, dst, ew, y, agg);
    fin64_kernel<<<N_NODES / 32, 128>>>(x1, agg, cinv, c2_rw, c2_lb, x2);

    // conv3: y8 = relu(x2@pw+pb)@lw (width 5), scatter, finalize (no relu)
    cudaMemsetAsync(agg8, 0, sizeof(float) * N_NODES * 8, 0);
    proj_lw_kernel<5><<<N_NODES / 32, 128>>>(x2, c3_pw, c3_pb, c3_lw, y);
    scatter8_kernel<false><<<6250, 256>>>(src, dst, ew, y, agg8);
    fin3_kernel<<<N_NODES / 16, 128>>>(x2, agg8, cinv, c3_rw, c3_lb, out);
}

// round 2
// speedup vs baseline: 1.0877x; 1.0877x over previous
#include <cuda_runtime.h>
#include <cstdint>
#include <math.h>

#define N_NODES 100000
#define N_EDGES 3200000
#define EPS_BN 1e-5f
#define EPS_NORM 1e-12f

// ---------------- device scratch (no allocation allowed) ----------------
__device__ __align__(16) float g_x0[N_NODES * 8];    // BN output (padded stride 8)
__device__ __align__(16) float g_x1[N_NODES * 64];   // conv1 output
__device__ __align__(16) float g_x2[N_NODES * 64];   // conv2 output
__device__ __align__(16) float g_y[N_NODES * 64];    // scatter source buffer (stride 64 or 8)
__device__ __align__(16) float g_agg[N_NODES * 64];  // conv2 accumulator
__device__ __align__(32) float g_agg8[N_NODES * 8];  // conv1/conv3 accumulator (5 feats + cnt)
__device__ float g_cinv[N_NODES];                    // 1/max(cnt,1)
__device__ float g_bnstats[16];                      // [0..4] sum, [5..9] sumsq

// ---------------- vector reductions ----------------
__device__ __forceinline__ void red_add_v4(float* p, float4 v) {
    asm volatile("red.global.add.v4.f32 [%0], {%1,%2,%3,%4};"
                 :: "l"(p), "f"(v.x), "f"(v.y), "f"(v.z), "f"(v.w) : "memory");
}
__device__ __forceinline__ void red_add_v2(float* p, float a, float b) {
    asm volatile("red.global.add.v2.f32 [%0], {%1,%2};"
                 :: "l"(p), "f"(a), "f"(b) : "memory");
}
__device__ __forceinline__ void red_add_f32(float* p, float a) {
    asm volatile("red.global.add.f32 [%0], %1;"
                 :: "l"(p), "f"(a) : "memory");
}

// ---------------- BatchNorm statistics ----------------
__global__ void bn_stats_kernel(const float* __restrict__ h) {
    float s[5] = {0, 0, 0, 0, 0}, q[5] = {0, 0, 0, 0, 0};
    int stride = gridDim.x * blockDim.x;
    for (int n = blockIdx.x * blockDim.x + threadIdx.x; n < N_NODES; n += stride) {
#pragma unroll
        for (int i = 0; i < 5; i++) {
            float v = h[n * 5 + i];
            s[i] += v;
            q[i] += v * v;
        }
    }
#pragma unroll
    for (int k = 16; k > 0; k >>= 1) {
#pragma unroll
        for (int i = 0; i < 5; i++) {
            s[i] += __shfl_down_sync(0xffffffffu, s[i], k);
            q[i] += __shfl_down_sync(0xffffffffu, q[i], k);
        }
    }
    __shared__ float sh[10];
    if (threadIdx.x < 10) sh[threadIdx.x] = 0.f;
    __syncthreads();
    if ((threadIdx.x & 31) == 0) {
#pragma unroll
        for (int i = 0; i < 5; i++) {
            atomicAdd(&sh[i], s[i]);
            atomicAdd(&sh[5 + i], q[i]);
        }
    }
    __syncthreads();
    if (threadIdx.x < 10) atomicAdd(&g_bnstats[threadIdx.x], sh[threadIdx.x]);
}

// ------- BN apply + conv1 projection (5x5) -> y8 ; zero agg8 row -------
__global__ void bn_conv1_kernel(const float* __restrict__ h,
                                const float* __restrict__ gamma,
                                const float* __restrict__ beta,
                                const float* __restrict__ pw,
                                const float* __restrict__ pb,
                                float* __restrict__ x0p,
                                float* __restrict__ y8,
                                float* __restrict__ agg8) {
    int n = blockIdx.x * blockDim.x + threadIdx.x;
    if (n >= N_NODES) return;
    const float inv_n = 1.f / (float)N_NODES;
    float xr[5];
#pragma unroll
    for (int i = 0; i < 5; i++) {
        float mu = g_bnstats[i] * inv_n;
        float var = g_bnstats[5 + i] * inv_n - mu * mu;
        float sc = rsqrtf(var + EPS_BN) * gamma[i];
        xr[i] = (h[n * 5 + i] - mu) * sc + beta[i];
    }
    float4* x0v = reinterpret_cast<float4*>(x0p + (size_t)n * 8);
    x0v[0] = make_float4(xr[0], xr[1], xr[2], xr[3]);
    x0v[1] = make_float4(xr[4], 0.f, 0.f, 0.f);
    float xp[5];
#pragma unroll
    for (int k = 0; k < 5; k++) {
        float v = pb[k];
#pragma unroll
        for (int i = 0; i < 5; i++) v += xr[i] * pw[i * 5 + k];
        xp[k] = fmaxf(v, 0.f);
    }
    float4* yv = reinterpret_cast<float4*>(y8 + (size_t)n * 8);
    yv[0] = make_float4(xp[0], xp[1], xp[2], xp[3]);
    yv[1] = make_float4(xp[4], 0.f, 0.f, 0.f);
    float4* av = reinterpret_cast<float4*>(agg8 + (size_t)n * 8);
    float4 z = make_float4(0.f, 0.f, 0.f, 0.f);
    av[0] = z;
    av[1] = z;
}

// ---------------- width-8 scatter (conv1 with cnt, conv3 without) ----------------
template <bool ADD_CNT>
__global__ void scatter8_kernel(const int* __restrict__ src,
                                const int* __restrict__ dst,
                                const float* __restrict__ ew,
                                const float* __restrict__ y8,
                                float* __restrict__ agg8) {
    int stride = gridDim.x * blockDim.x;
    for (int e = blockIdx.x * blockDim.x + threadIdx.x; e < N_EDGES; e += stride) {
        int s = __ldg(&src[e]);
        int d = __ldg(&dst[e]);
        float w = __ldg(&ew[e]);
        const float4* yv = reinterpret_cast<const float4*>(y8 + (size_t)s * 8);
        float4 a = yv[0];
        float4 b = yv[1];
        a.x *= w; a.y *= w; a.z *= w; a.w *= w;
        red_add_v4(agg8 + (size_t)d * 8, a);
        if (ADD_CNT)
            red_add_v2(agg8 + (size_t)d * 8 + 4, b.x * w, 1.0f);
        else
            red_add_f32(agg8 + (size_t)d * 8 + 4, b.x * w);
    }
}

// ---------------- width-64 scatter (conv2): warp handles 2 edges ----------------
__global__ void scatter64_kernel(const int* __restrict__ src,
                                 const int* __restrict__ dst,
                                 const float* __restrict__ ew,
                                 const float* __restrict__ y,
                                 float* __restrict__ agg) {
    int lane = threadIdx.x & 31;
    int warp = (blockIdx.x * blockDim.x + threadIdx.x) >> 5;
    int nwarps = (gridDim.x * blockDim.x) >> 5;
    int half = lane >> 4;
    int f = (lane & 15) << 2;
    const int npairs = N_EDGES / 2;
    for (int p = warp; p < npairs; p += nwarps) {
        int e = 2 * p + half;
        int s = __ldg(&src[e]);
        int d = __ldg(&dst[e]);
        float w = __ldg(&ew[e]);
        float4 v = *reinterpret_cast<const float4*>(y + (size_t)s * 64 + f);
        v.x *= w; v.y *= w; v.z *= w; v.w *= w;
        red_add_v4(agg + (size_t)d * 64 + f, v);
    }
}

// ------- conv1 finalize: out64 = mean5@lw + lb + x0@rw ; norm ; relu -------
// one node per thread; weights staged in shared (broadcast LDS.128)
__global__ __launch_bounds__(128) void fin1_kernel(const float* __restrict__ x0p,
                                                   const float* __restrict__ agg8,
                                                   const float* __restrict__ lw,
                                                   const float* __restrict__ lb,
                                                   const float* __restrict__ rw,
                                                   float* __restrict__ x1,
                                                   float* __restrict__ cinv_out) {
    __shared__ float4 s_lw[80], s_rw[80], s_lb[16];
    int t = threadIdx.x;
    if (t < 80) {
        s_lw[t] = reinterpret_cast<const float4*>(lw)[t];
        s_rw[t] = reinterpret_cast<const float4*>(rw)[t];
    }
    if (t < 16) s_lb[t] = reinterpret_cast<const float4*>(lb)[t];
    __syncthreads();
    int n = blockIdx.x * 128 + t;
    if (n >= N_NODES) return;

    const float4* av = reinterpret_cast<const float4*>(agg8 + (size_t)n * 8);
    float4 a0 = av[0], a1 = av[1];
    float ci = 1.f / fmaxf(a1.y, 1.f);
    cinv_out[n] = ci;
    float m[5] = {a0.x * ci, a0.y * ci, a0.z * ci, a0.w * ci, a1.x * ci};
    const float4* xv = reinterpret_cast<const float4*>(x0p + (size_t)n * 8);
    float4 x0a = xv[0], x0b = xv[1];
    float xr[5] = {x0a.x, x0a.y, x0a.z, x0a.w, x0b.x};

    float4 outv[16];
    float ss = 0.f;
#pragma unroll
    for (int oq = 0; oq < 16; oq++) {
        float4 v = s_lb[oq];
#pragma unroll
        for (int i = 0; i < 5; i++) {
            float4 w1 = s_lw[i * 16 + oq];
            float4 w2 = s_rw[i * 16 + oq];
            v.x += m[i] * w1.x + xr[i] * w2.x;
            v.y += m[i] * w1.y + xr[i] * w2.y;
            v.z += m[i] * w1.z + xr[i] * w2.z;
            v.w += m[i] * w1.w + xr[i] * w2.w;
        }
        outv[oq] = v;
        ss += v.x * v.x + v.y * v.y + v.z * v.z + v.w * v.w;
    }
    float sc = 1.f / fmaxf(sqrtf(ss), EPS_NORM);
    float4* xo = reinterpret_cast<float4*>(x1 + (size_t)n * 64);
#pragma unroll
    for (int oq = 0; oq < 16; oq++) {
        float4 v = outv[oq];
        xo[oq] = make_float4(fmaxf(v.x * sc, 0.f), fmaxf(v.y * sc, 0.f),
                             fmaxf(v.z * sc, 0.f), fmaxf(v.w * sc, 0.f));
    }
}

// ---------------- y = relu(x@pw + pb) @ lw  (64 -> 64 -> OUT2) ----------------
// optionally zeroes a per-block slice of an accumulator (for next scatter)
template <int OUT2>
__global__ __launch_bounds__(128) void proj_lw_kernel(const float* __restrict__ x,
                                                      const float* __restrict__ pw,
                                                      const float* __restrict__ pb,
                                                      const float* __restrict__ lw,
                                                      float* __restrict__ y,
                                                      float* __restrict__ zero_base,
                                                      int zero_f4_per_blk) {
    constexpr int OUTP = (OUT2 == 64) ? 64 : 8;
    constexpr int YS = (OUT2 == 64) ? 64 : 8;
    constexpr int NPB = 32;
    constexpr int XS = 36;
    __shared__ float s_w[64 * 64];
    __shared__ float s_x[64 * XS];
    __shared__ float s_xp[64 * XS];
    __shared__ float s_pb[64];
    const int t = threadIdx.x;
    const int n0 = blockIdx.x * NPB;

    if (zero_base) {
        float4 z = make_float4(0.f, 0.f, 0.f, 0.f);
        float4* zb = reinterpret_cast<float4*>(zero_base) + (size_t)blockIdx.x * zero_f4_per_blk;
        for (int i = t; i < zero_f4_per_blk; i += 128) zb[i] = z;
    }

    for (int i4 = t; i4 < 1024; i4 += 128)
        reinterpret_cast<float4*>(s_w)[i4] = reinterpret_cast<const float4*>(pw)[i4];
    if (t < 64) s_pb[t] = pb[t];
    for (int idx = t; idx < NPB * 64; idx += 128) {
        int n = idx >> 6, i = idx & 63;
        s_x[i * XS + n] = x[(size_t)(n0 + n) * 64 + i];
    }
    __syncthreads();

    const int oq = t & 15, nq = t >> 4;
    float acc[4][4];
#pragma unroll
    for (int a = 0; a < 4; a++)
#pragma unroll
        for (int b = 0; b < 4; b++) acc[a][b] = 0.f;

#pragma unroll 8
    for (int i = 0; i < 64; i++) {
        float4 xv = *reinterpret_cast<const float4*>(&s_x[i * XS + (nq << 2)]);
        float4 wv = *reinterpret_cast<const float4*>(&s_w[(i << 6) + (oq << 2)]);
        acc[0][0] += xv.x * wv.x; acc[0][1] += xv.x * wv.y; acc[0][2] += xv.x * wv.z; acc[0][3] += xv.x * wv.w;
        acc[1][0] += xv.y * wv.x; acc[1][1] += xv.y * wv.y; acc[1][2] += xv.y * wv.z; acc[1][3] += xv.y * wv.w;
        acc[2][0] += xv.z * wv.x; acc[2][1] += xv.z * wv.y; acc[2][2] += xv.z * wv.z; acc[2][3] += xv.z * wv.w;
        acc[3][0] += xv.w * wv.x; acc[3][1] += xv.w * wv.y; acc[3][2] += xv.w * wv.z; acc[3][3] += xv.w * wv.w;
    }
#pragma unroll
    for (int dk = 0; dk < 4; dk++) {
        float b = s_pb[(oq << 2) + dk];
#pragma unroll
        for (int dn = 0; dn < 4; dn++) {
            s_xp[((oq << 2) + dk) * XS + (nq << 2) + dn] = fmaxf(acc[dn][dk] + b, 0.f);
        }
    }
    __syncthreads();

    if (OUT2 == 64) {
        for (int i4 = t; i4 < 1024; i4 += 128)
            reinterpret_cast<float4*>(s_w)[i4] = reinterpret_cast<const float4*>(lw)[i4];
    } else {
        for (int idx = t; idx < 64 * 8; idx += 128) s_w[idx] = 0.f;
        __syncthreads();
        for (int idx = t; idx < 64 * 5; idx += 128) s_w[(idx / 5) * 8 + (idx % 5)] = lw[idx];
    }
    __syncthreads();

    constexpr int OQ2 = OUTP / 4;
    if (oq < OQ2) {
        float a2[4][4];
#pragma unroll
        for (int a = 0; a < 4; a++)
#pragma unroll
            for (int b = 0; b < 4; b++) a2[a][b] = 0.f;
#pragma unroll 8
        for (int i = 0; i < 64; i++) {
            float4 xv = *reinterpret_cast<const float4*>(&s_xp[i * XS + (nq << 2)]);
            float4 wv = *reinterpret_cast<const float4*>(&s_w[i * OUTP + (oq << 2)]);
            a2[0][0] += xv.x * wv.x; a2[0][1] += xv.x * wv.y; a2[0][2] += xv.x * wv.z; a2[0][3] += xv.x * wv.w;
            a2[1][0] += xv.y * wv.x; a2[1][1] += xv.y * wv.y; a2[1][2] += xv.y * wv.z; a2[1][3] += xv.y * wv.w;
            a2[2][0] += xv.z * wv.x; a2[2][1] += xv.z * wv.y; a2[2][2] += xv.z * wv.z; a2[2][3] += xv.z * wv.w;
            a2[3][0] += xv.w * wv.x; a2[3][1] += xv.w * wv.y; a2[3][2] += xv.w * wv.z; a2[3][3] += xv.w * wv.w;
        }
#pragma unroll
        for (int dn = 0; dn < 4; dn++) {
            float4 o4 = make_float4(a2[dn][0], a2[dn][1], a2[dn][2], a2[dn][3]);
            *reinterpret_cast<float4*>(&y[(size_t)(n0 + (nq << 2) + dn) * YS + (oq << 2)]) = o4;
        }
    }
}

// ------- conv2 finalize: out = agg*cinv + lb + x@rw ; norm ; relu ; zero agg8 -------
__global__ __launch_bounds__(128) void fin64_kernel(const float* __restrict__ x,
                                                    const float* __restrict__ agg,
                                                    const float* __restrict__ cinv,
                                                    const float* __restrict__ rw,
                                                    const float* __restrict__ lb,
                                                    float* __restrict__ out,
                                                    float* __restrict__ agg8z) {
    constexpr int NPB = 32;
    constexpr int XS = 36;
    __shared__ float s_w[64 * 64];
    __shared__ float s_x[64 * XS];
    __shared__ float s_lb[64];
    const int t = threadIdx.x;
    const int n0 = blockIdx.x * NPB;

    if (t < 64) {
        float4 z = make_float4(0.f, 0.f, 0.f, 0.f);
        reinterpret_cast<float4*>(agg8z + (size_t)n0 * 8)[t] = z;
    }

    for (int i4 = t; i4 < 1024; i4 += 128)
        reinterpret_cast<float4*>(s_w)[i4] = reinterpret_cast<const float4*>(rw)[i4];
    if (t < 64) s_lb[t] = lb[t];
    for (int idx = t; idx < NPB * 64; idx += 128) {
        int n = idx >> 6, i = idx & 63;
        s_x[i * XS + n] = x[(size_t)(n0 + n) * 64 + i];
    }
    __syncthreads();

    const int oq = t & 15, nq = t >> 4;
    float acc[4][4];
#pragma unroll
    for (int a = 0; a < 4; a++)
#pragma unroll
        for (int b = 0; b < 4; b++) acc[a][b] = 0.f;
#pragma unroll 8
    for (int i = 0; i < 64; i++) {
        float4 xv = *reinterpret_cast<const float4*>(&s_x[i * XS + (nq << 2)]);
        float4 wv = *reinterpret_cast<const float4*>(&s_w[(i << 6) + (oq << 2)]);
        acc[0][0] += xv.x * wv.x; acc[0][1] += xv.x * wv.y; acc[0][2] += xv.x * wv.z; acc[0][3] += xv.x * wv.w;
        acc[1][0] += xv.y * wv.x; acc[1][1] += xv.y * wv.y; acc[1][2] += xv.y * wv.z; acc[1][3] += xv.y * wv.w;
        acc[2][0] += xv.z * wv.x; acc[2][1] += xv.z * wv.y; acc[2][2] += xv.z * wv.z; acc[2][3] += xv.z * wv.w;
        acc[3][0] += xv.w * wv.x; acc[3][1] += xv.w * wv.y; acc[3][2] += xv.w * wv.z; acc[3][3] += xv.w * wv.w;
    }

    float lb0 = s_lb[(oq << 2) + 0], lb1 = s_lb[(oq << 2) + 1];
    float lb2 = s_lb[(oq << 2) + 2], lb3 = s_lb[(oq << 2) + 3];
#pragma unroll
    for (int dn = 0; dn < 4; dn++) {
        int n = n0 + (nq << 2) + dn;
        float ci = cinv[n];
        float4 ag = *reinterpret_cast<const float4*>(&agg[(size_t)n * 64 + (oq << 2)]);
        float v0 = acc[dn][0] + lb0 + ag.x * ci;
        float v1 = acc[dn][1] + lb1 + ag.y * ci;
        float v2 = acc[dn][2] + lb2 + ag.z * ci;
        float v3 = acc[dn][3] + lb3 + ag.w * ci;
        float ss = v0 * v0 + v1 * v1 + v2 * v2 + v3 * v3;
        ss += __shfl_down_sync(0xffffffffu, ss, 8, 16);
        ss += __shfl_down_sync(0xffffffffu, ss, 4, 16);
        ss += __shfl_down_sync(0xffffffffu, ss, 2, 16);
        ss += __shfl_down_sync(0xffffffffu, ss, 1, 16);
        ss = __shfl_sync(0xffffffffu, ss, 0, 16);
        float sc = 1.f / fmaxf(sqrtf(ss), EPS_NORM);
        float4 o4 = make_float4(fmaxf(v0 * sc, 0.f), fmaxf(v1 * sc, 0.f),
                                fmaxf(v2 * sc, 0.f), fmaxf(v3 * sc, 0.f));
        *reinterpret_cast<float4*>(&out[(size_t)n * 64 + (oq << 2)]) = o4;
    }
}

// ------- conv3 finalize: out5 = agg*cinv + lb + x2@rw ; norm (no relu) -------
// one node per thread
__global__ __launch_bounds__(128) void fin3_kernel(const float* __restrict__ x2,
                                                   const float* __restrict__ agg8,
                                                   const float* __restrict__ cinv,
                                                   const float* __restrict__ rw,
                                                   const float* __restrict__ lb,
                                                   float* __restrict__ out) {
    __shared__ float s_rw[64 * 8];
    __shared__ float s_lb[8];
    int t = threadIdx.x;
    for (int idx = t; idx < 320; idx += 128) s_rw[(idx / 5) * 8 + (idx % 5)] = rw[idx];
    if (t < 5) s_lb[t] = lb[t];
    __syncthreads();
    int n = blockIdx.x * 128 + t;
    if (n >= N_NODES) return;

    float ci = cinv[n];
    const float4* av = reinterpret_cast<const float4*>(agg8 + (size_t)n * 8);
    float4 a0 = av[0], a1 = av[1];
    float4 vf = make_float4(s_lb[0] + a0.x * ci, s_lb[1] + a0.y * ci,
                            s_lb[2] + a0.z * ci, s_lb[3] + a0.w * ci);
    float v4 = s_lb[4] + a1.x * ci;

    const float4* xr = reinterpret_cast<const float4*>(x2 + (size_t)n * 64);
#pragma unroll
    for (int iq = 0; iq < 16; iq++) {
        float4 xv = xr[iq];
        float xs[4] = {xv.x, xv.y, xv.z, xv.w};
#pragma unroll
        for (int c = 0; c < 4; c++) {
            int i = iq * 4 + c;
            float4 w = *reinterpret_cast<const float4*>(&s_rw[i * 8]);
            float w4 = s_rw[i * 8 + 4];
            vf.x += xs[c] * w.x;
            vf.y += xs[c] * w.y;
            vf.z += xs[c] * w.z;
            vf.w += xs[c] * w.w;
            v4 += xs[c] * w4;
        }
    }
    float ss = vf.x * vf.x + vf.y * vf.y + vf.z * vf.z + vf.w * vf.w + v4 * v4;
    float sc = 1.f / fmaxf(sqrtf(ss), EPS_NORM);
    float* o = out + (size_t)n * 5;
    o[0] = vf.x * sc;
    o[1] = vf.y * sc;
    o[2] = vf.z * sc;
    o[3] = vf.w * sc;
    o[4] = v4 * sc;
}

// ---------------- host launcher ----------------
extern "C" void kernel_launch(void* const* d_in, const int* in_sizes, int n_in,
                              void* d_out, int out_size) {
    const float* h = (const float*)d_in[0];
    const int* ei = (const int*)d_in[1];
    const float* ew = (const float*)d_in[2];
    const float* gamma = (const float*)d_in[3];
    const float* beta = (const float*)d_in[4];
    const float* c1_pw = (const float*)d_in[5];
    const float* c1_pb = (const float*)d_in[6];
    const float* c1_lw = (const float*)d_in[7];
    const float* c1_lb = (const float*)d_in[8];
    const float* c1_rw = (const float*)d_in[9];
    const float* c2_pw = (const float*)d_in[10];
    const float* c2_pb = (const float*)d_in[11];
    const float* c2_lw = (const float*)d_in[12];
    const float* c2_lb = (const float*)d_in[13];
    const float* c2_rw = (const float*)d_in[14];
    const float* c3_pw = (const float*)d_in[15];
    const float* c3_pb = (const float*)d_in[16];
    const float* c3_lw = (const float*)d_in[17];
    const float* c3_lb = (const float*)d_in[18];
    const float* c3_rw = (const float*)d_in[19];
    float* out = (float*)d_out;

    const int* src = ei;
    const int* dst = ei + N_EDGES;

    float *x0, *x1, *x2, *y, *agg, *agg8, *cinv, *stats;
    cudaGetSymbolAddress((void**)&x0, g_x0);
    cudaGetSymbolAddress((void**)&x1, g_x1);
    cudaGetSymbolAddress((void**)&x2, g_x2);
    cudaGetSymbolAddress((void**)&y, g_y);
    cudaGetSymbolAddress((void**)&agg, g_agg);
    cudaGetSymbolAddress((void**)&agg8, g_agg8);
    cudaGetSymbolAddress((void**)&cinv, g_cinv);
    cudaGetSymbolAddress((void**)&stats, g_bnstats);

    cudaMemsetAsync(stats, 0, sizeof(float) * 16, 0);

    // BatchNorm + conv1 projection (also zeroes agg8)
    bn_stats_kernel<<<128, 256>>>(h);
    bn_conv1_kernel<<<(N_NODES + 255) / 256, 256>>>(h, gamma, beta, c1_pw, c1_pb, x0, y, agg8);

    // conv1: scatter xp (width 5) + cnt, finalize
    scatter8_kernel<true><<<6250, 256>>>(src, dst, ew, y, agg8);
    fin1_kernel<<<(N_NODES + 127) / 128, 128>>>(x0, agg8, c1_lw, c1_lb, c1_rw, x1, cinv);

    // conv2: y = relu(x1@pw+pb)@lw (width 64), scatter, finalize
    // proj also zeroes agg (512 float4 per block = 32 rows of 64 floats)
    proj_lw_kernel<64><<<N_NODES / 32, 128>>>(x1, c2_pw, c2_pb, c2_lw, y, agg, 512);
    scatter64_kernel<<<4096, 256>>>(src, dst, ew, y, agg);
    fin64_kernel<<<N_NODES / 32, 128>>>(x1, agg, cinv, c2_rw, c2_lb, x2, agg8);

    // conv3: y8 = relu(x2@pw+pb)@lw (width 5), scatter, finalize (no relu)
    proj_lw_kernel<5><<<N_NODES / 32, 128>>>(x2, c3_pw, c3_pb, c3_lw, y, nullptr, 0);
    scatter8_kernel<false><<<6250, 256>>>(src, dst, ew, y, agg8);
    fin3_kernel<<<(N_NODES + 127) / 128, 128>>>(x2, agg8, cinv, c3_rw, c3_lb, out);
}